// round 13
// baseline (speedup 1.0000x reference)
#include <cuda_runtime.h>

// RiRoIAlign for GB300 — tap-parallel gather, 2x2 bin tiles, precomputed
// schedule table (no divides in hot loop), unroll-2 for MLP.
// features: (B=2, Ctot=256, H=256, W=256) fp32
// rois: (512, 6) fp32 = [batch, cx, cy, w, h, theta]
// out: (512, 256, 7, 7) fp32, channel = c*8 + o  (C=32, O=8)

#define HH 256
#define WW 256
#define CT 256
#define OO 8
#define NBIN 49
#define NS 196
#define HW (HH * WW)
#define NITEM (OO * NBIN)        // 392
#define NOUT (2 * NITEM)         // 784

// snake permutation: j -> bin, grouping consecutive 4 j's into 2x2 tiles.
__device__ __forceinline__ int bin_perm(int j) {
    if (j < 42) {
        const int c = j / 14;
        const int t = j - c * 14;
        return (t >> 1) * 7 + 2 * c + (t & 1);
    }
    return (j - 42) * 7 + 6;
}

__global__ __launch_bounds__(256, 6)
void riroi_kernel(const float* __restrict__ features,
                  const float* __restrict__ rois,
                  float* __restrict__ out)
{
    __shared__ float4 sgeo[NS * 2];   // [s*2+side] = {offL(i), offH(i), wHY, wLY}
    __shared__ int2   sched[NITEM];   // {plane*HW, accIdx<<16 | bin*8}
    __shared__ float  acc[NOUT];

    const int r   = blockIdx.x;
    const int cg  = blockIdx.y;          // 16 channel pairs
    const int tid = threadIdx.x;

    const float b_f = rois[r * 6 + 0];
    const float cwv = rois[r * 6 + 1] * 0.125f;
    const float chv = rois[r * 6 + 2] * 0.125f;
    const float rw  = fmaxf(rois[r * 6 + 3] * 0.125f, 1.0f);
    const float rh  = fmaxf(rois[r * 6 + 4] * 0.125f, 1.0f);
    const float th  = rois[r * 6 + 5];
    const int   b   = (int)b_f;

    const float st  = sinf(th);
    const float ctt = cosf(th);

    const float indf   = (th * 8.0f) / 6.283185307179586f;
    const float indflo = floorf(indf);
    const float lv     = indf - indflo;
    const float rv     = 1.0f - lv;
    int ind = (int)indflo;
    ind = ((ind % 8) + 8) % 8;

    const float bin_h = rh / 7.0f;
    const float bin_w = rw / 7.0f;

    // ---- schedule table: g -> (plane*HW, accIdx, bin*8) ----
    for (int g = tid; g < NITEM; g += 256) {
        const int plane = g / NBIN;           // once per CTA, off hot path
        const int j     = g - plane * NBIN;
        const int bin   = bin_perm(j);
        sched[g] = make_int2(plane * HW, ((plane * NBIN + bin) << 16) | (bin * 8));
    }

    // ---- geometry, bin-major: s = bin*4 + (gy*2+gx) ----
    if (tid < NS) {
        const int s   = tid;
        const int gx  = s & 1;
        const int gy  = (s >> 1) & 1;
        const int bin = s >> 2;
        const int py  = bin / 7;
        const int px  = bin - py * 7;

        const float yy = -rh * 0.5f + ((float)py + ((float)gy + 0.5f) * 0.5f) * bin_h;
        const float xx = -rw * 0.5f + ((float)px + ((float)gx + 0.5f) * 0.5f) * bin_w;

        const float x = xx * ctt - yy * st + cwv;
        const float y = xx * st + yy * ctt + chv;

        const bool valid = (y > -1.0f) && (y < 256.0f) && (x > -1.0f) && (x < 256.0f);

        const float yc = fmaxf(y, 0.0f);
        const float xc = fmaxf(x, 0.0f);
        int yl = (int)yc;
        int xl = (int)xc;
        int yh, xh;
        float yv, xv;
        if (yl >= HH - 1) { yl = HH - 1; yh = HH - 1; yv = (float)(HH - 1); }
        else              { yh = yl + 1;              yv = yc; }
        if (xl >= WW - 1) { xl = WW - 1; xh = WW - 1; xv = (float)(WW - 1); }
        else              { xh = xl + 1;              xv = xc; }

        const float ly = yv - (float)yl;
        const float lx = xv - (float)xl;
        const float vm  = valid ? 1.0f : 0.0f;
        const float hyv = (1.0f - ly) * vm;
        const float lyv = ly * vm;
        const float hx  = 1.0f - lx;

        const int rowL = yl * WW;
        const int rowH = yh * WW;

        sgeo[2 * s + 0] = make_float4(__int_as_float(rowL + xl),
                                      __int_as_float(rowH + xl),
                                      hx * hyv, hx * lyv);
        sgeo[2 * s + 1] = make_float4(__int_as_float(rowL + xh),
                                      __int_as_float(rowH + xh),
                                      lx * hyv, lx * lyv);
    }
    __syncthreads();

    // base: features[b, cg*16 + {0,1}*8 + plane, :, :]
    const float* fbase = features + ((size_t)b * CT + (size_t)cg * 16) * (size_t)HW;

    const int warp = tid >> 5;
    const int lane = tid & 31;
    const int isub = lane >> 3;          // item within warp's group of 4
    const int sub8 = lane & 7;           // (sample(2b), side(1b)) within bin

    #pragma unroll 2
    for (int gBase = warp * 4; gBase < NITEM; gBase += 32) {
        const int g = gBase + isub;

        const int2 sc = sched[g];
        const float4 gg = sgeo[(sc.y & 0xFFFF) + sub8];
        const int offL  = __float_as_int(gg.x) + sc.x;
        const int offH  = __float_as_int(gg.y) + sc.x;

        const float t0L = __ldg(fbase + offL);
        const float t0H = __ldg(fbase + offH);
        const float t1L = __ldg(fbase + offL + OO * HW);
        const float t1H = __ldg(fbase + offH + OO * HW);

        float v0 = gg.z * t0L + gg.w * t0H;
        float v1 = gg.z * t1L + gg.w * t1H;

        // sum the 8 lanes (4 samples x 2 sides) of this bin
        v0 += __shfl_xor_sync(0xFFFFFFFFu, v0, 1);
        v1 += __shfl_xor_sync(0xFFFFFFFFu, v1, 1);
        v0 += __shfl_xor_sync(0xFFFFFFFFu, v0, 2);
        v1 += __shfl_xor_sync(0xFFFFFFFFu, v1, 2);
        v0 += __shfl_xor_sync(0xFFFFFFFFu, v0, 4);
        v1 += __shfl_xor_sync(0xFFFFFFFFu, v1, 4);

        if (sub8 == 0) {
            const int a = sc.y >> 16;
            acc[a]         = v0;
            acc[NITEM + a] = v1;
        }
    }
    __syncthreads();

    // out[r, cg*16 .. +16, 7, 7]: contiguous 784 floats; j = cc*392 + o*49 + bin.
    float* ob = out + ((size_t)r * CT + (size_t)cg * 16) * (size_t)NBIN;
    #pragma unroll
    for (int jj = 0; jj < 4; ++jj) {
        const int j = jj * 256 + tid;
        if (j < NOUT) {
            const int cc   = j / NITEM;
            const int rest = j - cc * NITEM;
            const int o    = rest / NBIN;
            const int bin  = rest - o * NBIN;
            const int p0i  = (o - ind + 8) & 7;
            const int p1i  = (p0i + 1) & 7;
            ob[j] = 0.25f * (rv * acc[cc * NITEM + p0i * NBIN + bin]
                           + lv * acc[cc * NITEM + p1i * NBIN + bin]);
        }
    }
}

extern "C" void kernel_launch(void* const* d_in, const int* in_sizes, int n_in,
                              void* d_out, int out_size)
{
    const float* features = (const float*)d_in[0];
    const float* rois     = (const float*)d_in[1];
    float*       out      = (float*)d_out;

    const int R = in_sizes[1] / 6;
    dim3 grid((unsigned)R, 16);
    riroi_kernel<<<grid, 256>>>(features, rois, out);
}

// round 14
// speedup vs baseline: 1.1014x; 1.1014x over previous
#include <cuda_runtime.h>

// RiRoIAlign for GB300 — tap-parallel gather + rotation-adaptive bin grouping.
// features: (B=2, Ctot=256, H=256, W=256) fp32
// rois: (512, 6) fp32 = [batch, cx, cy, w, h, theta]
// out: (512, 256, 7, 7) fp32, channel = c*8 + o  (C=32, O=8)
//
// grid = (512 rois, 16 channel pairs). Warp = 4 (plane,bin) items, 8 lanes per
// bin = (sample(2b), x-side(1b)); geometry fused per (sample,side) into one
// float4 {offL, offH, wx*hy*vm, wx*ly*vm}. The 4 bins of a warp pass are
// grouped to minimize IMAGE-ROW span given the ROI rotation:
//   mode 0: 1x4 strip along px  (ROI x-axis near image-horizontal)
//   mode 1: 2x2 tile            (diagonal)
//   mode 2: 4x1 strip along py  (ROI x-axis near image-vertical)
// chosen per CTA by argmin of the predicted span — CTA-uniform branch.

#define HH 256
#define WW 256
#define CT 256
#define OO 8
#define NBIN 49
#define NS 196
#define HW (HH * WW)
#define NITEM (OO * NBIN)        // 392
#define NOUT (2 * NITEM)         // 784

__global__ __launch_bounds__(256, 6)
void riroi_kernel(const float* __restrict__ features,
                  const float* __restrict__ rois,
                  float* __restrict__ out)
{
    __shared__ float4 sgeo[NS * 2];   // [s*2+side] = {offL(i), offH(i), wHY, wLY}
    __shared__ float  acc[NOUT];

    const int r   = blockIdx.x;
    const int cg  = blockIdx.y;          // 16 channel pairs
    const int tid = threadIdx.x;

    const float b_f = rois[r * 6 + 0];
    const float cwv = rois[r * 6 + 1] * 0.125f;
    const float chv = rois[r * 6 + 2] * 0.125f;
    const float rw  = fmaxf(rois[r * 6 + 3] * 0.125f, 1.0f);
    const float rh  = fmaxf(rois[r * 6 + 4] * 0.125f, 1.0f);
    const float th  = rois[r * 6 + 5];
    const int   b   = (int)b_f;

    const float st  = sinf(th);
    const float ctt = cosf(th);

    const float indf   = (th * 8.0f) / 6.283185307179586f;
    const float indflo = floorf(indf);
    const float lv     = indf - indflo;
    const float rv     = 1.0f - lv;
    int ind = (int)indflo;
    ind = ((ind % 8) + 8) % 8;

    const float bin_h = rh / 7.0f;
    const float bin_w = rw / 7.0f;

    // ---- adaptive grouping mode (CTA-uniform) ----
    const float as = fabsf(st), ac = fabsf(ctt);
    const float wy = bin_w * as;          // image-y per px step
    const float hy_ = bin_h * ac;         // image-y per py step
    const float cost0 = 4.0f * wy + hy_;  // 1x4 along px
    const float cost1 = 2.0f * (wy + hy_);// 2x2
    const float cost2 = wy + 4.0f * hy_;  // 4x1 along py
    int mode = 1;
    float best = cost1;
    if (cost0 < best) { best = cost0; mode = 0; }
    if (cost2 < best) { mode = 2; }

    // ---- geometry, bin-major: s = bin*4 + (gy*2+gx) ----
    if (tid < NS) {
        const int s   = tid;
        const int gx  = s & 1;
        const int gy  = (s >> 1) & 1;
        const int bin = s >> 2;
        const int py  = bin / 7;
        const int px  = bin - py * 7;

        const float yy = -rh * 0.5f + ((float)py + ((float)gy + 0.5f) * 0.5f) * bin_h;
        const float xx = -rw * 0.5f + ((float)px + ((float)gx + 0.5f) * 0.5f) * bin_w;

        const float x = xx * ctt - yy * st + cwv;
        const float y = xx * st + yy * ctt + chv;

        const bool valid = (y > -1.0f) && (y < 256.0f) && (x > -1.0f) && (x < 256.0f);

        const float yc = fmaxf(y, 0.0f);
        const float xc = fmaxf(x, 0.0f);
        int yl = (int)yc;
        int xl = (int)xc;
        int yh, xh;
        float yv, xv;
        if (yl >= HH - 1) { yl = HH - 1; yh = HH - 1; yv = (float)(HH - 1); }
        else              { yh = yl + 1;              yv = yc; }
        if (xl >= WW - 1) { xl = WW - 1; xh = WW - 1; xv = (float)(WW - 1); }
        else              { xh = xl + 1;              xv = xc; }

        const float ly = yv - (float)yl;
        const float lx = xv - (float)xl;
        const float vm  = valid ? 1.0f : 0.0f;
        const float hyv = (1.0f - ly) * vm;
        const float lyv = ly * vm;
        const float hx  = 1.0f - lx;

        const int rowL = yl * WW;
        const int rowH = yh * WW;

        sgeo[2 * s + 0] = make_float4(__int_as_float(rowL + xl),
                                      __int_as_float(rowH + xl),
                                      hx * hyv, hx * lyv);
        sgeo[2 * s + 1] = make_float4(__int_as_float(rowL + xh),
                                      __int_as_float(rowH + xh),
                                      lx * hyv, lx * lyv);
    }
    __syncthreads();

    // base: features[b, cg*16 + {0,1}*8 + plane, :, :]
    const float* fbase = features + ((size_t)b * CT + (size_t)cg * 16) * (size_t)HW;

    const int warp = tid >> 5;
    const int lane = tid & 31;
    const int isub = lane >> 3;          // item within warp's group of 4
    const int sub8 = lane & 7;           // (sample(2b), side(1b)) within bin

    for (int gBase = warp * 4; gBase < NITEM; gBase += 32) {
        const int g     = gBase + isub;
        const int plane = g / NBIN;
        const int j     = g - plane * NBIN;

        // CTA-uniform mode -> no divergence
        int bin;
        if (mode == 0) {
            bin = j;                              // natural: 1x4 px strips
        } else if (mode == 1) {
            if (j < 42) {                         // 2x2 snake over column pairs
                const int c = j / 14;
                const int t = j - c * 14;
                bin = (t >> 1) * 7 + 2 * c + (t & 1);
            } else {
                bin = (j - 42) * 7 + 6;
            }
        } else {
            const int px = j / 7;                 // transpose: 4x1 py strips
            bin = (j - px * 7) * 7 + px;
        }

        const float4 gg = sgeo[bin * 8 + sub8];
        const int offL  = __float_as_int(gg.x);
        const int offH  = __float_as_int(gg.y);

        const float* p0 = fbase + plane * HW;
        const float* p1 = p0 + OO * HW;

        const float t0L = __ldg(p0 + offL);
        const float t0H = __ldg(p0 + offH);
        const float t1L = __ldg(p1 + offL);
        const float t1H = __ldg(p1 + offH);

        float v0 = gg.z * t0L + gg.w * t0H;
        float v1 = gg.z * t1L + gg.w * t1H;

        // sum the 8 lanes (4 samples x 2 sides) of this bin
        v0 += __shfl_xor_sync(0xFFFFFFFFu, v0, 1);
        v1 += __shfl_xor_sync(0xFFFFFFFFu, v1, 1);
        v0 += __shfl_xor_sync(0xFFFFFFFFu, v0, 2);
        v1 += __shfl_xor_sync(0xFFFFFFFFu, v1, 2);
        v0 += __shfl_xor_sync(0xFFFFFFFFu, v0, 4);
        v1 += __shfl_xor_sync(0xFFFFFFFFu, v1, 4);

        if (sub8 == 0) {
            const int a = plane * NBIN + bin;
            acc[a]         = v0;
            acc[NITEM + a] = v1;
        }
    }
    __syncthreads();

    // out[r, cg*16 .. +16, 7, 7]: contiguous 784 floats; j = cc*392 + o*49 + bin.
    float* ob = out + ((size_t)r * CT + (size_t)cg * 16) * (size_t)NBIN;
    #pragma unroll
    for (int jj = 0; jj < 4; ++jj) {
        const int j = jj * 256 + tid;
        if (j < NOUT) {
            const int cc   = j / NITEM;
            const int rest = j - cc * NITEM;
            const int o    = rest / NBIN;
            const int bin  = rest - o * NBIN;
            const int p0i  = (o - ind + 8) & 7;
            const int p1i  = (p0i + 1) & 7;
            ob[j] = 0.25f * (rv * acc[cc * NITEM + p0i * NBIN + bin]
                           + lv * acc[cc * NITEM + p1i * NBIN + bin]);
        }
    }
}

extern "C" void kernel_launch(void* const* d_in, const int* in_sizes, int n_in,
                              void* d_out, int out_size)
{
    const float* features = (const float*)d_in[0];
    const float* rois     = (const float*)d_in[1];
    float*       out      = (float*)d_out;

    const int R = in_sizes[1] / 6;
    dim3 grid((unsigned)R, 16);
    riroi_kernel<<<grid, 256>>>(features, rois, out);
}

// round 15
// speedup vs baseline: 1.1692x; 1.0616x over previous
#include <cuda_runtime.h>

// RiRoIAlign for GB300 — tap-parallel gather, rotation-adaptive bin grouping,
// channel-interleaved shuffle reduction (4 SHFL per pass instead of 6).
// features: (B=2, Ctot=256, H=256, W=256) fp32
// rois: (512, 6) fp32 = [batch, cx, cy, w, h, theta]
// out: (512, 256, 7, 7) fp32, channel = c*8 + o  (C=32, O=8)
//
// grid = (512 rois, 16 channel pairs). Warp = 4 (plane,bin) items, 8 lanes per
// bin = (sample(2b), x-side(1b)); geometry fused per (sample,side) into one
// float4 {offL, offH, wx*hy*vm, wx*ly*vm}. Warp bin groups chosen per ROI
// rotation (1x4 / 2x2 / 4x1) to minimize image-row span per LDG instruction.
// Reduction: level-1 exchange folds ch0 into even lanes, ch1 into odd lanes;
// xor-2 / xor-4 finish both channels with a single value per lane.

#define HH 256
#define WW 256
#define CT 256
#define OO 8
#define NBIN 49
#define NS 196
#define HW (HH * WW)
#define NITEM (OO * NBIN)        // 392
#define NOUT (2 * NITEM)         // 784

__global__ __launch_bounds__(256, 6)
void riroi_kernel(const float* __restrict__ features,
                  const float* __restrict__ rois,
                  float* __restrict__ out)
{
    __shared__ float4 sgeo[NS * 2];   // [s*2+side] = {offL(i), offH(i), wHY, wLY}
    __shared__ float  acc[NOUT];

    const int r   = blockIdx.x;
    const int cg  = blockIdx.y;          // 16 channel pairs
    const int tid = threadIdx.x;

    const float b_f = rois[r * 6 + 0];
    const float cwv = rois[r * 6 + 1] * 0.125f;
    const float chv = rois[r * 6 + 2] * 0.125f;
    const float rw  = fmaxf(rois[r * 6 + 3] * 0.125f, 1.0f);
    const float rh  = fmaxf(rois[r * 6 + 4] * 0.125f, 1.0f);
    const float th  = rois[r * 6 + 5];
    const int   b   = (int)b_f;

    const float st  = sinf(th);
    const float ctt = cosf(th);

    const float indf   = (th * 8.0f) / 6.283185307179586f;
    const float indflo = floorf(indf);
    const float lv     = indf - indflo;
    const float rv     = 1.0f - lv;
    int ind = (int)indflo;
    ind = ((ind % 8) + 8) % 8;

    const float bin_h = rh / 7.0f;
    const float bin_w = rw / 7.0f;

    // ---- adaptive grouping mode (CTA-uniform) ----
    const float as = fabsf(st), ac = fabsf(ctt);
    const float wy  = bin_w * as;          // image-y per px step
    const float hy_ = bin_h * ac;          // image-y per py step
    const float cost0 = 4.0f * wy + hy_;   // 1x4 along px
    const float cost1 = 2.0f * (wy + hy_); // 2x2
    const float cost2 = wy + 4.0f * hy_;   // 4x1 along py
    int mode = 1;
    float best = cost1;
    if (cost0 < best) { best = cost0; mode = 0; }
    if (cost2 < best) { mode = 2; }

    // ---- geometry, bin-major: s = bin*4 + (gy*2+gx) ----
    if (tid < NS) {
        const int s   = tid;
        const int gx  = s & 1;
        const int gy  = (s >> 1) & 1;
        const int bin = s >> 2;
        const int py  = bin / 7;
        const int px  = bin - py * 7;

        const float yy = -rh * 0.5f + ((float)py + ((float)gy + 0.5f) * 0.5f) * bin_h;
        const float xx = -rw * 0.5f + ((float)px + ((float)gx + 0.5f) * 0.5f) * bin_w;

        const float x = xx * ctt - yy * st + cwv;
        const float y = xx * st + yy * ctt + chv;

        const bool valid = (y > -1.0f) && (y < 256.0f) && (x > -1.0f) && (x < 256.0f);

        const float yc = fmaxf(y, 0.0f);
        const float xc = fmaxf(x, 0.0f);
        int yl = (int)yc;
        int xl = (int)xc;
        int yh, xh;
        float yv, xv;
        if (yl >= HH - 1) { yl = HH - 1; yh = HH - 1; yv = (float)(HH - 1); }
        else              { yh = yl + 1;              yv = yc; }
        if (xl >= WW - 1) { xl = WW - 1; xh = WW - 1; xv = (float)(WW - 1); }
        else              { xh = xl + 1;              xv = xc; }

        const float ly = yv - (float)yl;
        const float lx = xv - (float)xl;
        const float vm  = valid ? 1.0f : 0.0f;
        const float hyv = (1.0f - ly) * vm;
        const float lyv = ly * vm;
        const float hx  = 1.0f - lx;

        const int rowL = yl * WW;
        const int rowH = yh * WW;

        sgeo[2 * s + 0] = make_float4(__int_as_float(rowL + xl),
                                      __int_as_float(rowH + xl),
                                      hx * hyv, hx * lyv);
        sgeo[2 * s + 1] = make_float4(__int_as_float(rowL + xh),
                                      __int_as_float(rowH + xh),
                                      lx * hyv, lx * lyv);
    }
    __syncthreads();

    // base: features[b, cg*16 + {0,1}*8 + plane, :, :]
    const float* fbase = features + ((size_t)b * CT + (size_t)cg * 16) * (size_t)HW;

    const int warp = tid >> 5;
    const int lane = tid & 31;
    const int isub = lane >> 3;          // item within warp's group of 4
    const int sub8 = lane & 7;           // (sample(2b), side(1b)) within bin

    for (int gBase = warp * 4; gBase < NITEM; gBase += 32) {
        const int g     = gBase + isub;
        const int plane = g / NBIN;
        const int j     = g - plane * NBIN;

        // CTA-uniform mode -> no divergence
        int bin;
        if (mode == 0) {
            bin = j;                              // natural: 1x4 px strips
        } else if (mode == 1) {
            if (j < 42) {                         // 2x2 snake over column pairs
                const int c = j / 14;
                const int t = j - c * 14;
                bin = (t >> 1) * 7 + 2 * c + (t & 1);
            } else {
                bin = (j - 42) * 7 + 6;
            }
        } else {
            const int px = j / 7;                 // transpose: 4x1 py strips
            bin = (j - px * 7) * 7 + px;
        }

        const float4 gg = sgeo[bin * 8 + sub8];
        const int offL  = __float_as_int(gg.x);
        const int offH  = __float_as_int(gg.y);

        const float* p0 = fbase + plane * HW;
        const float* p1 = p0 + OO * HW;

        const float t0L = __ldg(p0 + offL);
        const float t0H = __ldg(p0 + offH);
        const float t1L = __ldg(p1 + offL);
        const float t1H = __ldg(p1 + offH);

        const float v0 = gg.z * t0L + gg.w * t0H;
        const float v1 = gg.z * t1L + gg.w * t1H;

        // channel-interleaved reduction over the 8 lanes of this bin:
        // level 1 folds lane pairs AND selects channel by lane parity
        // (even lanes carry ch0, odd lanes carry ch1), then xor-2/xor-4
        // reduce within each parity class.
        const float e0 = __shfl_xor_sync(0xFFFFFFFFu, v0, 1);
        const float e1 = __shfl_xor_sync(0xFFFFFFFFu, v1, 1);
        float a = (lane & 1) ? (v1 + e1) : (v0 + e0);
        a += __shfl_xor_sync(0xFFFFFFFFu, a, 2);
        a += __shfl_xor_sync(0xFFFFFFFFu, a, 4);

        if (sub8 < 2) {
            const int aidx = plane * NBIN + bin;
            acc[aidx + (sub8 & 1) * NITEM] = a;   // lane0 -> ch0, lane1 -> ch1
        }
    }
    __syncthreads();

    // out[r, cg*16 .. +16, 7, 7]: contiguous 784 floats; j = cc*392 + o*49 + bin.
    float* ob = out + ((size_t)r * CT + (size_t)cg * 16) * (size_t)NBIN;
    #pragma unroll
    for (int jj = 0; jj < 4; ++jj) {
        const int j = jj * 256 + tid;
        if (j < NOUT) {
            const int cc   = j / NITEM;
            const int rest = j - cc * NITEM;
            const int o    = rest / NBIN;
            const int bin  = rest - o * NBIN;
            const int p0i  = (o - ind + 8) & 7;
            const int p1i  = (p0i + 1) & 7;
            ob[j] = 0.25f * (rv * acc[cc * NITEM + p0i * NBIN + bin]
                           + lv * acc[cc * NITEM + p1i * NBIN + bin]);
        }
    }
}

extern "C" void kernel_launch(void* const* d_in, const int* in_sizes, int n_in,
                              void* d_out, int out_size)
{
    const float* features = (const float*)d_in[0];
    const float* rois     = (const float*)d_in[1];
    float*       out      = (float*)d_out;

    const int R = in_sizes[1] / 6;
    dim3 grid((unsigned)R, 16);
    riroi_kernel<<<grid, 256>>>(features, rois, out);
}

// round 16
// speedup vs baseline: 1.2484x; 1.0677x over previous
#include <cuda_runtime.h>

// RiRoIAlign for GB300 — tap-parallel gather, rotation-adaptive bin grouping,
// plane-innermost loop (geometry register-cached), channel-interleaved
// shuffle reduction.
// features: (B=2, Ctot=256, H=256, W=256) fp32
// rois: (512, 6) fp32 = [batch, cx, cy, w, h, theta]
// out: (512, 256, 7, 7) fp32, channel = c*8 + o  (C=32, O=8)
//
// grid = (512 rois, 16 channel pairs). Warp owns a fixed group of 4 bins
// (8 lanes per bin: sample(2b) x side(1b)) and loops the 8 orientation planes
// innermost, so the fused geometry float4 {offL, offH, wHY, wLY} is loaded
// from smem ONCE per bin-group and reused 8x from registers. The 4-bin group
// shape adapts to ROI rotation (1x4 / 2x2 / 4x1) to minimize image-row span
// per LDG instruction.

#define HH 256
#define WW 256
#define CT 256
#define OO 8
#define NBIN 49
#define NS 196
#define HW (HH * WW)
#define NITEM (OO * NBIN)        // 392
#define NOUT (2 * NITEM)         // 784

__global__ __launch_bounds__(256, 6)
void riroi_kernel(const float* __restrict__ features,
                  const float* __restrict__ rois,
                  float* __restrict__ out)
{
    __shared__ float4 sgeo[NS * 2];   // [s*2+side] = {offL(i), offH(i), wHY, wLY}
    __shared__ float  acc[NOUT];

    const int r   = blockIdx.x;
    const int cg  = blockIdx.y;          // 16 channel pairs
    const int tid = threadIdx.x;

    const float b_f = rois[r * 6 + 0];
    const float cwv = rois[r * 6 + 1] * 0.125f;
    const float chv = rois[r * 6 + 2] * 0.125f;
    const float rw  = fmaxf(rois[r * 6 + 3] * 0.125f, 1.0f);
    const float rh  = fmaxf(rois[r * 6 + 4] * 0.125f, 1.0f);
    const float th  = rois[r * 6 + 5];
    const int   b   = (int)b_f;

    const float st  = sinf(th);
    const float ctt = cosf(th);

    const float indf   = (th * 8.0f) / 6.283185307179586f;
    const float indflo = floorf(indf);
    const float lv     = indf - indflo;
    const float rv     = 1.0f - lv;
    int ind = (int)indflo;
    ind = ((ind % 8) + 8) % 8;

    const float bin_h = rh / 7.0f;
    const float bin_w = rw / 7.0f;

    // ---- adaptive grouping mode (CTA-uniform) ----
    const float as = fabsf(st), ac = fabsf(ctt);
    const float wy  = bin_w * as;          // image-y per px step
    const float hy_ = bin_h * ac;          // image-y per py step
    const float cost0 = 4.0f * wy + hy_;   // 1x4 along px
    const float cost1 = 2.0f * (wy + hy_); // 2x2
    const float cost2 = wy + 4.0f * hy_;   // 4x1 along py
    int mode = 1;
    float best = cost1;
    if (cost0 < best) { best = cost0; mode = 0; }
    if (cost2 < best) { mode = 2; }

    // ---- geometry, bin-major: s = bin*4 + (gy*2+gx) ----
    if (tid < NS) {
        const int s   = tid;
        const int gx  = s & 1;
        const int gy  = (s >> 1) & 1;
        const int bin = s >> 2;
        const int py  = bin / 7;
        const int px  = bin - py * 7;

        const float yy = -rh * 0.5f + ((float)py + ((float)gy + 0.5f) * 0.5f) * bin_h;
        const float xx = -rw * 0.5f + ((float)px + ((float)gx + 0.5f) * 0.5f) * bin_w;

        const float x = xx * ctt - yy * st + cwv;
        const float y = xx * st + yy * ctt + chv;

        const bool valid = (y > -1.0f) && (y < 256.0f) && (x > -1.0f) && (x < 256.0f);

        const float yc = fmaxf(y, 0.0f);
        const float xc = fmaxf(x, 0.0f);
        int yl = (int)yc;
        int xl = (int)xc;
        int yh, xh;
        float yv, xv;
        if (yl >= HH - 1) { yl = HH - 1; yh = HH - 1; yv = (float)(HH - 1); }
        else              { yh = yl + 1;              yv = yc; }
        if (xl >= WW - 1) { xl = WW - 1; xh = WW - 1; xv = (float)(WW - 1); }
        else              { xh = xl + 1;              xv = xc; }

        const float ly = yv - (float)yl;
        const float lx = xv - (float)xl;
        const float vm  = valid ? 1.0f : 0.0f;
        const float hyv = (1.0f - ly) * vm;
        const float lyv = ly * vm;
        const float hx  = 1.0f - lx;

        const int rowL = yl * WW;
        const int rowH = yh * WW;

        sgeo[2 * s + 0] = make_float4(__int_as_float(rowL + xl),
                                      __int_as_float(rowH + xl),
                                      hx * hyv, hx * lyv);
        sgeo[2 * s + 1] = make_float4(__int_as_float(rowL + xh),
                                      __int_as_float(rowH + xh),
                                      lx * hyv, lx * lyv);
    }
    __syncthreads();

    // base: features[b, cg*16 + {0,1}*8 + plane, :, :]
    const float* fbase = features + ((size_t)b * CT + (size_t)cg * 16) * (size_t)HW;

    const int warp = tid >> 5;
    const int lane = tid & 31;
    const int isub = lane >> 3;          // bin within warp's group of 4
    const int sub8 = lane & 7;           // (sample(2b), side(1b)) within bin

    // warp owns bin-group jb (4 bins), loops 8 planes inside.
    for (int jb = warp * 4; jb < NBIN; jb += 32) {
        const int j  = jb + isub;                 // may reach 51 at jb=48
        const int jc = (j < NBIN) ? j : (NBIN - 1);

        // CTA-uniform mode -> no divergence
        int bin;
        if (mode == 0) {
            bin = jc;                             // natural: 1x4 px strips
        } else if (mode == 1) {
            if (jc < 42) {                        // 2x2 snake over column pairs
                const int c = jc / 14;
                const int t = jc - c * 14;
                bin = (t >> 1) * 7 + 2 * c + (t & 1);
            } else {
                bin = (jc - 42) * 7 + 6;
            }
        } else {
            const int px = jc / 7;                // transpose: 4x1 py strips
            bin = (jc - px * 7) * 7 + px;
        }

        const float4 gg = sgeo[bin * 8 + sub8];   // ONE LDS.128 per bin-group
        const int offL  = __float_as_int(gg.x);
        const int offH  = __float_as_int(gg.y);
        const bool wr   = (sub8 < 2) && (j < NBIN);
        const int  aidx = bin + (sub8 & 1) * NITEM;

        const float* p0 = fbase;
        #pragma unroll 2
        for (int plane = 0; plane < OO; ++plane) {
            const float t0L = __ldg(p0 + offL);
            const float t0H = __ldg(p0 + offH);
            const float t1L = __ldg(p0 + OO * HW + offL);
            const float t1H = __ldg(p0 + OO * HW + offH);

            const float v0 = gg.z * t0L + gg.w * t0H;
            const float v1 = gg.z * t1L + gg.w * t1H;

            // channel-interleaved 8-lane reduction (ch0 -> even, ch1 -> odd)
            const float e0 = __shfl_xor_sync(0xFFFFFFFFu, v0, 1);
            const float e1 = __shfl_xor_sync(0xFFFFFFFFu, v1, 1);
            float a = (lane & 1) ? (v1 + e1) : (v0 + e0);
            a += __shfl_xor_sync(0xFFFFFFFFu, a, 2);
            a += __shfl_xor_sync(0xFFFFFFFFu, a, 4);

            if (wr) acc[plane * NBIN + aidx] = a;
            p0 += HW;
        }
    }
    __syncthreads();

    // out[r, cg*16 .. +16, 7, 7]: contiguous 784 floats; j = cc*392 + o*49 + bin.
    float* ob = out + ((size_t)r * CT + (size_t)cg * 16) * (size_t)NBIN;
    #pragma unroll
    for (int jj = 0; jj < 4; ++jj) {
        const int j = jj * 256 + tid;
        if (j < NOUT) {
            const int cc   = j / NITEM;
            const int rest = j - cc * NITEM;
            const int o    = rest / NBIN;
            const int bin  = rest - o * NBIN;
            const int p0i  = (o - ind + 8) & 7;
            const int p1i  = (p0i + 1) & 7;
            ob[j] = 0.25f * (rv * acc[cc * NITEM + p0i * NBIN + bin]
                           + lv * acc[cc * NITEM + p1i * NBIN + bin]);
        }
    }
}

extern "C" void kernel_launch(void* const* d_in, const int* in_sizes, int n_in,
                              void* d_out, int out_size)
{
    const float* features = (const float*)d_in[0];
    const float* rois     = (const float*)d_in[1];
    float*       out      = (float*)d_out;

    const int R = in_sizes[1] / 6;
    dim3 grid((unsigned)R, 16);
    riroi_kernel<<<grid, 256>>>(features, rois, out);
}

// round 17
// speedup vs baseline: 1.2537x; 1.0042x over previous
#include <cuda_runtime.h>

// RiRoIAlign for GB300 — tap-parallel gather, rotation-adaptive bin grouping,
// plane-innermost loop, channel-interleaved reduction, 224-thread CTAs for
// balanced bin-group distribution (13 groups over 7 warps = 6x2 + 1x1).
// features: (B=2, Ctot=256, H=256, W=256) fp32
// rois: (512, 6) fp32 = [batch, cx, cy, w, h, theta]
// out: (512, 256, 7, 7) fp32, channel = c*8 + o  (C=32, O=8)

#define HH 256
#define WW 256
#define CT 256
#define OO 8
#define NBIN 49
#define NS 196
#define HW (HH * WW)
#define NITEM (OO * NBIN)        // 392
#define NOUT (2 * NITEM)         // 784
#define NT 224                   // 7 warps

__global__ __launch_bounds__(NT, 7)
void riroi_kernel(const float* __restrict__ features,
                  const float* __restrict__ rois,
                  float* __restrict__ out)
{
    __shared__ float4 sgeo[NS * 2];   // [s*2+side] = {offL(i), offH(i), wHY, wLY}
    __shared__ float  acc[NOUT];

    const int r   = blockIdx.x;
    const int cg  = blockIdx.y;          // 16 channel pairs
    const int tid = threadIdx.x;

    const float b_f = rois[r * 6 + 0];
    const float cwv = rois[r * 6 + 1] * 0.125f;
    const float chv = rois[r * 6 + 2] * 0.125f;
    const float rw  = fmaxf(rois[r * 6 + 3] * 0.125f, 1.0f);
    const float rh  = fmaxf(rois[r * 6 + 4] * 0.125f, 1.0f);
    const float th  = rois[r * 6 + 5];
    const int   b   = (int)b_f;

    const float st  = sinf(th);
    const float ctt = cosf(th);

    const float indf   = (th * 8.0f) / 6.283185307179586f;
    const float indflo = floorf(indf);
    const float lv     = indf - indflo;
    const float rv     = 1.0f - lv;
    int ind = (int)indflo;
    ind = ((ind % 8) + 8) % 8;

    const float bin_h = rh / 7.0f;
    const float bin_w = rw / 7.0f;

    // ---- adaptive grouping mode (CTA-uniform) ----
    const float as = fabsf(st), ac = fabsf(ctt);
    const float wyc  = bin_w * as;          // image-y per px step
    const float hyc  = bin_h * ac;          // image-y per py step
    const float cost0 = 4.0f * wyc + hyc;   // 1x4 along px
    const float cost1 = 2.0f * (wyc + hyc); // 2x2
    const float cost2 = wyc + 4.0f * hyc;   // 4x1 along py
    int mode = 1;
    float best = cost1;
    if (cost0 < best) { best = cost0; mode = 0; }
    if (cost2 < best) { mode = 2; }

    // ---- geometry, bin-major: s = bin*4 + (gy*2+gx) ----
    if (tid < NS) {
        const int s   = tid;
        const int gx  = s & 1;
        const int gy  = (s >> 1) & 1;
        const int bin = s >> 2;
        const int py  = bin / 7;
        const int px  = bin - py * 7;

        const float yy = -rh * 0.5f + ((float)py + ((float)gy + 0.5f) * 0.5f) * bin_h;
        const float xx = -rw * 0.5f + ((float)px + ((float)gx + 0.5f) * 0.5f) * bin_w;

        const float x = xx * ctt - yy * st + cwv;
        const float y = xx * st + yy * ctt + chv;

        const bool valid = (y > -1.0f) && (y < 256.0f) && (x > -1.0f) && (x < 256.0f);

        const float yc = fmaxf(y, 0.0f);
        const float xc = fmaxf(x, 0.0f);
        int yl = (int)yc;
        int xl = (int)xc;
        int yh, xh;
        float yv, xv;
        if (yl >= HH - 1) { yl = HH - 1; yh = HH - 1; yv = (float)(HH - 1); }
        else              { yh = yl + 1;              yv = yc; }
        if (xl >= WW - 1) { xl = WW - 1; xh = WW - 1; xv = (float)(WW - 1); }
        else              { xh = xl + 1;              xv = xc; }

        const float ly = yv - (float)yl;
        const float lx = xv - (float)xl;
        const float vm  = valid ? 1.0f : 0.0f;
        const float hyv = (1.0f - ly) * vm;
        const float lyv = ly * vm;
        const float hx  = 1.0f - lx;

        const int rowL = yl * WW;
        const int rowH = yh * WW;

        sgeo[2 * s + 0] = make_float4(__int_as_float(rowL + xl),
                                      __int_as_float(rowH + xl),
                                      hx * hyv, hx * lyv);
        sgeo[2 * s + 1] = make_float4(__int_as_float(rowL + xh),
                                      __int_as_float(rowH + xh),
                                      lx * hyv, lx * lyv);
    }
    __syncthreads();

    // base: features[b, cg*16 + {0,1}*8 + plane, :, :]
    const float* fbase = features + ((size_t)b * CT + (size_t)cg * 16) * (size_t)HW;

    const int warp = tid >> 5;
    const int lane = tid & 31;
    const int isub = lane >> 3;          // bin within warp's group of 4
    const int sub8 = lane & 7;           // (sample(2b), side(1b)) within bin

    // 13 groups over 7 warps: stride 28 bins per pass (6 warps x2 + 1 warp x1).
    for (int jb = warp * 4; jb < NBIN; jb += 28) {
        const int j  = jb + isub;                 // may reach 51 at jb=48
        const int jc = (j < NBIN) ? j : (NBIN - 1);

        // CTA-uniform mode -> no divergence
        int bin;
        if (mode == 0) {
            bin = jc;                             // natural: 1x4 px strips
        } else if (mode == 1) {
            if (jc < 42) {                        // 2x2 snake over column pairs
                const int c = jc / 14;
                const int t = jc - c * 14;
                bin = (t >> 1) * 7 + 2 * c + (t & 1);
            } else {
                bin = (jc - 42) * 7 + 6;
            }
        } else {
            const int px = jc / 7;                // transpose: 4x1 py strips
            bin = (jc - px * 7) * 7 + px;
        }

        const float4 gg = sgeo[bin * 8 + sub8];   // ONE LDS.128 per bin-group
        const int offL  = __float_as_int(gg.x);
        const int offH  = __float_as_int(gg.y);
        const bool wr   = (sub8 < 2) && (j < NBIN);
        const int  aidx = bin + (sub8 & 1) * NITEM;

        const float* p0 = fbase;
        #pragma unroll 2
        for (int plane = 0; plane < OO; ++plane) {
            const float t0L = __ldg(p0 + offL);
            const float t0H = __ldg(p0 + offH);
            const float t1L = __ldg(p0 + OO * HW + offL);
            const float t1H = __ldg(p0 + OO * HW + offH);

            const float v0 = gg.z * t0L + gg.w * t0H;
            const float v1 = gg.z * t1L + gg.w * t1H;

            // channel-interleaved 8-lane reduction (ch0 -> even, ch1 -> odd)
            const float e0 = __shfl_xor_sync(0xFFFFFFFFu, v0, 1);
            const float e1 = __shfl_xor_sync(0xFFFFFFFFu, v1, 1);
            float a = (lane & 1) ? (v1 + e1) : (v0 + e0);
            a += __shfl_xor_sync(0xFFFFFFFFu, a, 2);
            a += __shfl_xor_sync(0xFFFFFFFFu, a, 4);

            if (wr) acc[plane * NBIN + aidx] = a;
            p0 += HW;
        }
    }
    __syncthreads();

    // out[r, cg*16 .. +16, 7, 7]: contiguous 784 floats; j = cc*392 + o*49 + bin.
    float* ob = out + ((size_t)r * CT + (size_t)cg * 16) * (size_t)NBIN;
    #pragma unroll
    for (int jj = 0; jj < 4; ++jj) {
        const int j = jj * NT + tid;
        if (j < NOUT) {
            const int cc   = j / NITEM;
            const int rest = j - cc * NITEM;
            const int o    = rest / NBIN;
            const int bin  = rest - o * NBIN;
            const int p0i  = (o - ind + 8) & 7;
            const int p1i  = (p0i + 1) & 7;
            ob[j] = 0.25f * (rv * acc[cc * NITEM + p0i * NBIN + bin]
                           + lv * acc[cc * NITEM + p1i * NBIN + bin]);
        }
    }
}

extern "C" void kernel_launch(void* const* d_in, const int* in_sizes, int n_in,
                              void* d_out, int out_size)
{
    const float* features = (const float*)d_in[0];
    const float* rois     = (const float*)d_in[1];
    float*       out      = (float*)d_out;

    const int R = in_sizes[1] / 6;
    dim3 grid((unsigned)R, 16);
    riroi_kernel<<<grid, NT>>>(features, rois, out);
}